// round 15
// baseline (speedup 1.0000x reference)
#include <cuda_runtime.h>
#include <cstdint>

// Problem constants
#define BB 64
#define NN 1024
#define CC 128
#define DD 64

// Scratch for Q, K, V (relu'd projections), fp32. __device__ globals (sanctioned scratch).
__device__ float g_Q[BB * NN * DD];
__device__ float g_K[BB * NN * DD];
__device__ float g_V[BB * NN * DD];

// Round fp32 -> tf32 (round-to-nearest) and return as a float bit-pattern.
__device__ __forceinline__ float f2tf(float f) {
    uint32_t u;
    asm("cvt.rna.tf32.f32 %0, %1;" : "=r"(u) : "f"(f));
    return __uint_as_float(u);
}

// m16n8k8 tf32 MMA, fp32 accumulate. A row-major, B col-major.
__device__ __forceinline__ void mma_tf32(float* d,
                                         uint32_t a0, uint32_t a1, uint32_t a2, uint32_t a3,
                                         uint32_t b0, uint32_t b1) {
    asm volatile(
        "mma.sync.aligned.m16n8k8.row.col.f32.tf32.tf32.f32 "
        "{%0,%1,%2,%3}, {%4,%5,%6,%7}, {%8,%9}, {%0,%1,%2,%3};"
        : "+f"(d[0]), "+f"(d[1]), "+f"(d[2]), "+f"(d[3])
        : "r"(a0), "r"(a1), "r"(a2), "r"(a3), "r"(b0), "r"(b1));
}

__device__ __forceinline__ void cp_async16(uint32_t smem_addr, const void* gptr) {
    asm volatile("cp.async.cg.shared.global [%0], [%1], 16;"
                 :: "r"(smem_addr), "l"(gptr));
}
__device__ __forceinline__ void cp_commit() {
    asm volatile("cp.async.commit_group;");
}

// ============================================================================
// Kernel 1: fused QKV projection.  q/k/v = relu(x @ W + b).
// 384 threads = 3 groups of 4 warps; group m computes matrix m for the SAME
// 128-row x tile (x loaded into smem ONCE -> 1/3 the x gmem traffic).
// Per warp: 32 rows x 64 cols (2 m-frags x 8 n-frags), identical MMA pattern
// to the R10 kernel.
// ============================================================================
__global__ __launch_bounds__(384) void qkv_kernel(
    const float* __restrict__ x,
    const float* __restrict__ Wq, const float* __restrict__ bq,
    const float* __restrict__ Wk, const float* __restrict__ bk,
    const float* __restrict__ Wv, const float* __restrict__ bv)
{
    __shared__ float xs[128 * 36];       // x chunk [128 rows][32 k], stride 36
    __shared__ float ws[3][32 * 72];     // W chunk per matrix [32 k][64 n], stride 72

    const int tid  = threadIdx.x;
    const int w    = tid >> 5;           // 0..11
    const int grp  = w >> 2;             // matrix: 0:Q 1:K 2:V
    const int wg   = w & 3;              // warp within group
    const int lt   = tid & 127;          // thread within group
    const int lane = tid & 31;
    const int g    = lane >> 2;
    const int t    = lane & 3;
    const int r0   = blockIdx.x * 128;

    const float* W    = (grp == 0) ? Wq : (grp == 1) ? Wk : Wv;
    const float* bias = (grp == 0) ? bq : (grp == 1) ? bk : bv;
    float* dst        = (grp == 0) ? g_Q : (grp == 1) ? g_K : g_V;

    float acc[2][8][4];
#pragma unroll
    for (int m = 0; m < 2; m++)
#pragma unroll
        for (int i = 0; i < 8; i++)
#pragma unroll
            for (int j = 0; j < 4; j++) acc[m][i][j] = 0.f;

    for (int kc = 0; kc < 4; kc++) {
        __syncthreads();
        // x chunk: 128x32 fp32 = 1024 float4 over 384 threads.
#pragma unroll
        for (int i = 0; i < 3; i++) {
            int v = tid + i * 384;
            if (v < 1024) {
                int row = v >> 3;
                int c4  = v & 7;
                float4 xv = *reinterpret_cast<const float4*>(
                    x + (size_t)(r0 + row) * CC + kc * 32 + c4 * 4);
                *reinterpret_cast<float4*>(&xs[row * 36 + c4 * 4]) =
                    make_float4(f2tf(xv.x), f2tf(xv.y), f2tf(xv.z), f2tf(xv.w));
            }
        }
        // W chunk: each group loads its own 32x64 = 512 float4 with 128 threads.
#pragma unroll
        for (int i = 0; i < 4; i++) {
            int v   = lt + i * 128;
            int row = v >> 4;
            int c4  = v & 15;
            float4 wv = *reinterpret_cast<const float4*>(
                W + (size_t)(kc * 32 + row) * DD + c4 * 4);
            *reinterpret_cast<float4*>(&ws[grp][row * 72 + c4 * 4]) =
                make_float4(f2tf(wv.x), f2tf(wv.y), f2tf(wv.z), f2tf(wv.w));
        }
        __syncthreads();

#pragma unroll
        for (int ksi = 0; ksi < 4; ksi++) {
            uint32_t a[2][4];
#pragma unroll
            for (int m = 0; m < 2; m++) {
                int ar = (wg * 32 + m * 16 + g) * 36 + ksi * 8 + t;
                a[m][0] = __float_as_uint(xs[ar]);
                a[m][1] = __float_as_uint(xs[ar + 8 * 36]);
                a[m][2] = __float_as_uint(xs[ar + 4]);
                a[m][3] = __float_as_uint(xs[ar + 8 * 36 + 4]);
            }
#pragma unroll
            for (int nf = 0; nf < 8; nf++) {
                uint32_t b0 = __float_as_uint(ws[grp][(ksi * 8 + t)     * 72 + nf * 8 + g]);
                uint32_t b1 = __float_as_uint(ws[grp][(ksi * 8 + t + 4) * 72 + nf * 8 + g]);
                mma_tf32(acc[0][nf], a[0][0], a[0][1], a[0][2], a[0][3], b0, b1);
                mma_tf32(acc[1][nf], a[1][0], a[1][1], a[1][2], a[1][3], b0, b1);
            }
        }
    }

#pragma unroll
    for (int m = 0; m < 2; m++) {
        const size_t rg = (size_t)r0 + wg * 32 + m * 16 + g;
#pragma unroll
        for (int nf = 0; nf < 8; nf++) {
            int dcol = nf * 8 + 2 * t;
            float b0v = bias[dcol], b1v = bias[dcol + 1];
            *reinterpret_cast<float2*>(dst + rg * DD + dcol) =
                make_float2(fmaxf(acc[m][nf][0] + b0v, 0.f),
                            fmaxf(acc[m][nf][1] + b1v, 0.f));
            *reinterpret_cast<float2*>(dst + (rg + 8) * DD + dcol) =
                make_float2(fmaxf(acc[m][nf][2] + b0v, 0.f),
                            fmaxf(acc[m][nf][3] + b1v, 0.f));
        }
    }
}

// ============================================================================
// Kernel 2: flash attention + residual.  out = softmax(Q Kt / 8) @ V + Q
// CTA = 128 q-rows (grid 8 x 64), 4 warps, warp = 32 rows (2 m-frags).
// Q in registers, pre-scaled by 0.125*log2(e) so P = exp2(S) (1 MUFU each)
// and K needs NO per-tile scaling. K/V tiles fetched with cp.async (LDGSTS,
// raw fp32; MMA truncates to tf32), double-buffered, prefetch depth 2.
// No max tracking (scores bounded since q,k >= 0). P stays in registers via
// the key-permutation trick.
// ============================================================================
__global__ __launch_bounds__(128) void attn_kernel(float* __restrict__ out)
{
    __shared__ __align__(16) float ksm[2][32 * 68];   // K tiles, raw fp32
    __shared__ __align__(16) float vsm[2][32 * 72];   // V tiles, raw fp32

    const int tid  = threadIdx.x;
    const int w    = tid >> 5;
    const int lane = tid & 31;
    const int g    = lane >> 2;
    const int t    = lane & 3;
    const int b    = blockIdx.y;
    const int qt   = blockIdx.x;
    const int pkg  = (g >> 1) | ((g & 1) << 2);   // key permutation within 8-group
    const size_t qbase = (size_t)b * NN + qt * 128 + w * 32;

    const int lrow = tid >> 4;
    const int lc4  = tid & 15;
    const float* kbase = g_K + (size_t)b * NN * DD;
    const float* vbase = g_V + (size_t)b * NN * DD;

    // Q fragments in registers, scaled by 1/8 * log2(e): S then feeds exp2.
    const float cq = 0.125f * 1.4426950408889634f;
    uint32_t qa[2][8][4];
#pragma unroll
    for (int m = 0; m < 2; m++) {
        const float* qb = g_Q + (qbase + m * 16) * DD;
#pragma unroll
        for (int ksi = 0; ksi < 8; ksi++) {
            qa[m][ksi][0] = __float_as_uint(f2tf(qb[(size_t)g * DD + ksi * 8 + t] * cq));
            qa[m][ksi][1] = __float_as_uint(f2tf(qb[(size_t)(g + 8) * DD + ksi * 8 + t] * cq));
            qa[m][ksi][2] = __float_as_uint(f2tf(qb[(size_t)g * DD + ksi * 8 + t + 4] * cq));
            qa[m][ksi][3] = __float_as_uint(f2tf(qb[(size_t)(g + 8) * DD + ksi * 8 + t + 4] * cq));
        }
    }

    float o[2][8][4];
#pragma unroll
    for (int m = 0; m < 2; m++)
#pragma unroll
        for (int i = 0; i < 8; i++)
#pragma unroll
            for (int j = 0; j < 4; j++) o[m][i][j] = 0.f;
    float ll[2][2] = {{0.f, 0.f}, {0.f, 0.f}};   // lane-local l partials [m][row-half]

    // cp.async tile issue: 4 K-rows + 4 V-rows of 16B per thread.
    auto issue_tile = [&](int tile, int buf) {
        const float* kb = kbase + (size_t)tile * 32 * DD;
        const float* vb = vbase + (size_t)tile * 32 * DD;
#pragma unroll
        for (int i = 0; i < 4; i++) {
            int row = lrow + i * 8;
            cp_async16((uint32_t)__cvta_generic_to_shared(&ksm[buf][row * 68 + lc4 * 4]),
                       kb + row * DD + lc4 * 4);
            cp_async16((uint32_t)__cvta_generic_to_shared(&vsm[buf][row * 72 + lc4 * 4]),
                       vb + row * DD + lc4 * 4);
        }
        cp_commit();
    };

    // Prologue: prefetch tiles 0 and 1.
    issue_tile(0, 0);
    issue_tile(1, 1);

    for (int kt = 0; kt < 32; kt++) {
        const int cur = kt & 1;

        // Wait for tile kt (1 younger group may remain in flight).
        if (kt < 31) {
            asm volatile("cp.async.wait_group 1;");
        } else {
            asm volatile("cp.async.wait_group 0;");
        }
        __syncthreads();   // cross-thread visibility of the async fills

        // ---- S = (Q*c) @ K^T : 32x32 per warp, keys permuted per 8-group ----
        float s[2][4][4];
#pragma unroll
        for (int m = 0; m < 2; m++)
#pragma unroll
            for (int i = 0; i < 4; i++)
#pragma unroll
                for (int j = 0; j < 4; j++) s[m][i][j] = 0.f;
#pragma unroll
        for (int ksi = 0; ksi < 8; ksi++) {
#pragma unroll
            for (int nf = 0; nf < 4; nf++) {
                int kr = (nf * 8 + pkg) * 68 + ksi * 8 + t;
                uint32_t b0 = __float_as_uint(ksm[cur][kr]);
                uint32_t b1 = __float_as_uint(ksm[cur][kr + 4]);
                mma_tf32(s[0][nf], qa[0][ksi][0], qa[0][ksi][1], qa[0][ksi][2], qa[0][ksi][3], b0, b1);
                mma_tf32(s[1][nf], qa[1][ksi][0], qa[1][ksi][1], qa[1][ksi][2], qa[1][ksi][3], b0, b1);
            }
        }

        // ---- P = exp2(S) (S pre-scaled by log2 e; bounded, no max needed) ----
#pragma unroll
        for (int m = 0; m < 2; m++) {
#pragma unroll
            for (int nf = 0; nf < 4; nf++) {
                s[m][nf][0] = f2tf(exp2f(s[m][nf][0]));
                s[m][nf][1] = f2tf(exp2f(s[m][nf][1]));
                s[m][nf][2] = f2tf(exp2f(s[m][nf][2]));
                s[m][nf][3] = f2tf(exp2f(s[m][nf][3]));
                ll[m][0] += s[m][nf][0] + s[m][nf][1];
                ll[m][1] += s[m][nf][2] + s[m][nf][3];
            }
        }

        // ---- O += P @ V : P straight from s (permutation-aligned) ----
#pragma unroll
        for (int k2 = 0; k2 < 4; k2++) {
#pragma unroll
            for (int nf = 0; nf < 8; nf++) {
                uint32_t b0 = __float_as_uint(vsm[cur][(k2 * 8 + t)     * 72 + nf * 8 + g]);
                uint32_t b1 = __float_as_uint(vsm[cur][(k2 * 8 + t + 4) * 72 + nf * 8 + g]);
                mma_tf32(o[0][nf],
                         __float_as_uint(s[0][k2][0]), __float_as_uint(s[0][k2][2]),
                         __float_as_uint(s[0][k2][1]), __float_as_uint(s[0][k2][3]), b0, b1);
                mma_tf32(o[1][nf],
                         __float_as_uint(s[1][k2][0]), __float_as_uint(s[1][k2][2]),
                         __float_as_uint(s[1][k2][1]), __float_as_uint(s[1][k2][3]), b0, b1);
            }
        }

        __syncthreads();   // all warps done reading buf cur before refilling it
        if (kt + 2 < 32) issue_tile(kt + 2, cur);
    }

    // ---- epilogue: reduce l across quad, normalize, add residual q ----
#pragma unroll
    for (int m = 0; m < 2; m++) {
        float l0 = ll[m][0], l1 = ll[m][1];
        l0 += __shfl_xor_sync(0xffffffffu, l0, 1);
        l0 += __shfl_xor_sync(0xffffffffu, l0, 2);
        l1 += __shfl_xor_sync(0xffffffffu, l1, 1);
        l1 += __shfl_xor_sync(0xffffffffu, l1, 2);
        float il0 = 1.f / l0, il1 = 1.f / l1;
        const size_t r0o = qbase + m * 16 + g;
        const size_t r1o = r0o + 8;
#pragma unroll
        for (int nf = 0; nf < 8; nf++) {
            int c = nf * 8 + 2 * t;
            float2 q0 = *reinterpret_cast<const float2*>(g_Q + r0o * DD + c);
            float2 q1 = *reinterpret_cast<const float2*>(g_Q + r1o * DD + c);
            *reinterpret_cast<float2*>(out + r0o * DD + c) =
                make_float2(o[m][nf][0] * il0 + q0.x, o[m][nf][1] * il0 + q0.y);
            *reinterpret_cast<float2*>(out + r1o * DD + c) =
                make_float2(o[m][nf][2] * il1 + q1.x, o[m][nf][3] * il1 + q1.y);
        }
    }
}

// ============================================================================
extern "C" void kernel_launch(void* const* d_in, const int* in_sizes, int n_in,
                              void* d_out, int out_size) {
    const float* x  = (const float*)d_in[0];
    const float* Wq = (const float*)d_in[1];
    const float* bq = (const float*)d_in[2];
    const float* Wk = (const float*)d_in[3];
    const float* bk = (const float*)d_in[4];
    const float* Wv = (const float*)d_in[5];
    const float* bv = (const float*)d_in[6];
    float* out = (float*)d_out;

    qkv_kernel<<<512, 384>>>(x, Wq, bq, Wk, bk, Wv, bv);
    attn_kernel<<<dim3(8, 64), 128>>>(out);
}

// round 16
// speedup vs baseline: 1.0014x; 1.0014x over previous
#include <cuda_runtime.h>
#include <cstdint>

// Problem constants
#define BB 64
#define NN 1024
#define CC 128
#define DD 64

// Scratch for Q, K, V (relu'd projections), fp32. __device__ globals (sanctioned scratch).
__device__ float g_Q[BB * NN * DD];
__device__ float g_K[BB * NN * DD];
__device__ float g_V[BB * NN * DD];

// Round fp32 -> tf32 (round-to-nearest) and return as a float bit-pattern.
__device__ __forceinline__ float f2tf(float f) {
    uint32_t u;
    asm("cvt.rna.tf32.f32 %0, %1;" : "=r"(u) : "f"(f));
    return __uint_as_float(u);
}

// m16n8k8 tf32 MMA, fp32 accumulate. A row-major, B col-major.
__device__ __forceinline__ void mma_tf32(float* d,
                                         uint32_t a0, uint32_t a1, uint32_t a2, uint32_t a3,
                                         uint32_t b0, uint32_t b1) {
    asm volatile(
        "mma.sync.aligned.m16n8k8.row.col.f32.tf32.tf32.f32 "
        "{%0,%1,%2,%3}, {%4,%5,%6,%7}, {%8,%9}, {%0,%1,%2,%3};"
        : "+f"(d[0]), "+f"(d[1]), "+f"(d[2]), "+f"(d[3])
        : "r"(a0), "r"(a1), "r"(a2), "r"(a3), "r"(b0), "r"(b1));
}

__device__ __forceinline__ void cp_async16(uint32_t smem_addr, const void* gptr) {
    asm volatile("cp.async.cg.shared.global [%0], [%1], 16;"
                 :: "r"(smem_addr), "l"(gptr));
}
__device__ __forceinline__ void cp_commit() {
    asm volatile("cp.async.commit_group;");
}

// ============================================================================
// Kernel 1: fused QKV projection.  q/k/v = relu(x @ W + b).
// 384 threads = 3 groups of 4 warps; group m computes matrix m for the SAME
// 128-row x tile (x loaded into smem ONCE -> 1/3 the x gmem traffic).
// Per warp: 32 rows x 64 cols (2 m-frags x 8 n-frags), identical MMA pattern
// to the R10 kernel.
// ============================================================================
__global__ __launch_bounds__(384) void qkv_kernel(
    const float* __restrict__ x,
    const float* __restrict__ Wq, const float* __restrict__ bq,
    const float* __restrict__ Wk, const float* __restrict__ bk,
    const float* __restrict__ Wv, const float* __restrict__ bv)
{
    __shared__ float xs[128 * 36];       // x chunk [128 rows][32 k], stride 36
    __shared__ float ws[3][32 * 72];     // W chunk per matrix [32 k][64 n], stride 72

    const int tid  = threadIdx.x;
    const int w    = tid >> 5;           // 0..11
    const int grp  = w >> 2;             // matrix: 0:Q 1:K 2:V
    const int wg   = w & 3;              // warp within group
    const int lt   = tid & 127;          // thread within group
    const int lane = tid & 31;
    const int g    = lane >> 2;
    const int t    = lane & 3;
    const int r0   = blockIdx.x * 128;

    const float* W    = (grp == 0) ? Wq : (grp == 1) ? Wk : Wv;
    const float* bias = (grp == 0) ? bq : (grp == 1) ? bk : bv;
    float* dst        = (grp == 0) ? g_Q : (grp == 1) ? g_K : g_V;

    float acc[2][8][4];
#pragma unroll
    for (int m = 0; m < 2; m++)
#pragma unroll
        for (int i = 0; i < 8; i++)
#pragma unroll
            for (int j = 0; j < 4; j++) acc[m][i][j] = 0.f;

    for (int kc = 0; kc < 4; kc++) {
        __syncthreads();
        // x chunk: 128x32 fp32 = 1024 float4 over 384 threads.
#pragma unroll
        for (int i = 0; i < 3; i++) {
            int v = tid + i * 384;
            if (v < 1024) {
                int row = v >> 3;
                int c4  = v & 7;
                float4 xv = *reinterpret_cast<const float4*>(
                    x + (size_t)(r0 + row) * CC + kc * 32 + c4 * 4);
                *reinterpret_cast<float4*>(&xs[row * 36 + c4 * 4]) =
                    make_float4(f2tf(xv.x), f2tf(xv.y), f2tf(xv.z), f2tf(xv.w));
            }
        }
        // W chunk: each group loads its own 32x64 = 512 float4 with 128 threads.
#pragma unroll
        for (int i = 0; i < 4; i++) {
            int v   = lt + i * 128;
            int row = v >> 4;
            int c4  = v & 15;
            float4 wv = *reinterpret_cast<const float4*>(
                W + (size_t)(kc * 32 + row) * DD + c4 * 4);
            *reinterpret_cast<float4*>(&ws[grp][row * 72 + c4 * 4]) =
                make_float4(f2tf(wv.x), f2tf(wv.y), f2tf(wv.z), f2tf(wv.w));
        }
        __syncthreads();

#pragma unroll
        for (int ksi = 0; ksi < 4; ksi++) {
            uint32_t a[2][4];
#pragma unroll
            for (int m = 0; m < 2; m++) {
                int ar = (wg * 32 + m * 16 + g) * 36 + ksi * 8 + t;
                a[m][0] = __float_as_uint(xs[ar]);
                a[m][1] = __float_as_uint(xs[ar + 8 * 36]);
                a[m][2] = __float_as_uint(xs[ar + 4]);
                a[m][3] = __float_as_uint(xs[ar + 8 * 36 + 4]);
            }
#pragma unroll
            for (int nf = 0; nf < 8; nf++) {
                uint32_t b0 = __float_as_uint(ws[grp][(ksi * 8 + t)     * 72 + nf * 8 + g]);
                uint32_t b1 = __float_as_uint(ws[grp][(ksi * 8 + t + 4) * 72 + nf * 8 + g]);
                mma_tf32(acc[0][nf], a[0][0], a[0][1], a[0][2], a[0][3], b0, b1);
                mma_tf32(acc[1][nf], a[1][0], a[1][1], a[1][2], a[1][3], b0, b1);
            }
        }
    }

#pragma unroll
    for (int m = 0; m < 2; m++) {
        const size_t rg = (size_t)r0 + wg * 32 + m * 16 + g;
#pragma unroll
        for (int nf = 0; nf < 8; nf++) {
            int dcol = nf * 8 + 2 * t;
            float b0v = bias[dcol], b1v = bias[dcol + 1];
            *reinterpret_cast<float2*>(dst + rg * DD + dcol) =
                make_float2(fmaxf(acc[m][nf][0] + b0v, 0.f),
                            fmaxf(acc[m][nf][1] + b1v, 0.f));
            *reinterpret_cast<float2*>(dst + (rg + 8) * DD + dcol) =
                make_float2(fmaxf(acc[m][nf][2] + b0v, 0.f),
                            fmaxf(acc[m][nf][3] + b1v, 0.f));
        }
    }
}

// ============================================================================
// Kernel 2: flash attention + residual.  out = softmax(Q Kt / 8) @ V + Q
// CTA = 128 q-rows (grid 8 x 64), 4 warps, warp = 32 rows (2 m-frags).
// Q in registers, pre-scaled by 0.125*log2(e) so P = exp2(S) (1 MUFU each)
// and K needs NO per-tile scaling. K/V tiles fetched with cp.async (LDGSTS,
// raw fp32; MMA truncates to tf32), double-buffered, prefetch depth 2.
// No max tracking (scores bounded since q,k >= 0). P stays in registers via
// the key-permutation trick.
// ============================================================================
__global__ __launch_bounds__(128) void attn_kernel(float* __restrict__ out)
{
    __shared__ __align__(16) float ksm[2][32 * 68];   // K tiles, raw fp32
    __shared__ __align__(16) float vsm[2][32 * 72];   // V tiles, raw fp32

    const int tid  = threadIdx.x;
    const int w    = tid >> 5;
    const int lane = tid & 31;
    const int g    = lane >> 2;
    const int t    = lane & 3;
    const int b    = blockIdx.y;
    const int qt   = blockIdx.x;
    const int pkg  = (g >> 1) | ((g & 1) << 2);   // key permutation within 8-group
    const size_t qbase = (size_t)b * NN + qt * 128 + w * 32;

    const int lrow = tid >> 4;
    const int lc4  = tid & 15;
    const float* kbase = g_K + (size_t)b * NN * DD;
    const float* vbase = g_V + (size_t)b * NN * DD;

    // Q fragments in registers, scaled by 1/8 * log2(e): S then feeds exp2.
    const float cq = 0.125f * 1.4426950408889634f;
    uint32_t qa[2][8][4];
#pragma unroll
    for (int m = 0; m < 2; m++) {
        const float* qb = g_Q + (qbase + m * 16) * DD;
#pragma unroll
        for (int ksi = 0; ksi < 8; ksi++) {
            qa[m][ksi][0] = __float_as_uint(f2tf(qb[(size_t)g * DD + ksi * 8 + t] * cq));
            qa[m][ksi][1] = __float_as_uint(f2tf(qb[(size_t)(g + 8) * DD + ksi * 8 + t] * cq));
            qa[m][ksi][2] = __float_as_uint(f2tf(qb[(size_t)g * DD + ksi * 8 + t + 4] * cq));
            qa[m][ksi][3] = __float_as_uint(f2tf(qb[(size_t)(g + 8) * DD + ksi * 8 + t + 4] * cq));
        }
    }

    float o[2][8][4];
#pragma unroll
    for (int m = 0; m < 2; m++)
#pragma unroll
        for (int i = 0; i < 8; i++)
#pragma unroll
            for (int j = 0; j < 4; j++) o[m][i][j] = 0.f;
    float ll[2][2] = {{0.f, 0.f}, {0.f, 0.f}};   // lane-local l partials [m][row-half]

    // cp.async tile issue: 4 K-rows + 4 V-rows of 16B per thread.
    auto issue_tile = [&](int tile, int buf) {
        const float* kb = kbase + (size_t)tile * 32 * DD;
        const float* vb = vbase + (size_t)tile * 32 * DD;
#pragma unroll
        for (int i = 0; i < 4; i++) {
            int row = lrow + i * 8;
            cp_async16((uint32_t)__cvta_generic_to_shared(&ksm[buf][row * 68 + lc4 * 4]),
                       kb + row * DD + lc4 * 4);
            cp_async16((uint32_t)__cvta_generic_to_shared(&vsm[buf][row * 72 + lc4 * 4]),
                       vb + row * DD + lc4 * 4);
        }
        cp_commit();
    };

    // Prologue: prefetch tiles 0 and 1.
    issue_tile(0, 0);
    issue_tile(1, 1);

    for (int kt = 0; kt < 32; kt++) {
        const int cur = kt & 1;

        // Wait for tile kt (1 younger group may remain in flight).
        if (kt < 31) {
            asm volatile("cp.async.wait_group 1;");
        } else {
            asm volatile("cp.async.wait_group 0;");
        }
        __syncthreads();   // cross-thread visibility of the async fills

        // ---- S = (Q*c) @ K^T : 32x32 per warp, keys permuted per 8-group ----
        float s[2][4][4];
#pragma unroll
        for (int m = 0; m < 2; m++)
#pragma unroll
            for (int i = 0; i < 4; i++)
#pragma unroll
                for (int j = 0; j < 4; j++) s[m][i][j] = 0.f;
#pragma unroll
        for (int ksi = 0; ksi < 8; ksi++) {
#pragma unroll
            for (int nf = 0; nf < 4; nf++) {
                int kr = (nf * 8 + pkg) * 68 + ksi * 8 + t;
                uint32_t b0 = __float_as_uint(ksm[cur][kr]);
                uint32_t b1 = __float_as_uint(ksm[cur][kr + 4]);
                mma_tf32(s[0][nf], qa[0][ksi][0], qa[0][ksi][1], qa[0][ksi][2], qa[0][ksi][3], b0, b1);
                mma_tf32(s[1][nf], qa[1][ksi][0], qa[1][ksi][1], qa[1][ksi][2], qa[1][ksi][3], b0, b1);
            }
        }

        // ---- P = exp2(S) (S pre-scaled by log2 e; bounded, no max needed) ----
#pragma unroll
        for (int m = 0; m < 2; m++) {
#pragma unroll
            for (int nf = 0; nf < 4; nf++) {
                s[m][nf][0] = f2tf(exp2f(s[m][nf][0]));
                s[m][nf][1] = f2tf(exp2f(s[m][nf][1]));
                s[m][nf][2] = f2tf(exp2f(s[m][nf][2]));
                s[m][nf][3] = f2tf(exp2f(s[m][nf][3]));
                ll[m][0] += s[m][nf][0] + s[m][nf][1];
                ll[m][1] += s[m][nf][2] + s[m][nf][3];
            }
        }

        // ---- O += P @ V : P straight from s (permutation-aligned) ----
#pragma unroll
        for (int k2 = 0; k2 < 4; k2++) {
#pragma unroll
            for (int nf = 0; nf < 8; nf++) {
                uint32_t b0 = __float_as_uint(vsm[cur][(k2 * 8 + t)     * 72 + nf * 8 + g]);
                uint32_t b1 = __float_as_uint(vsm[cur][(k2 * 8 + t + 4) * 72 + nf * 8 + g]);
                mma_tf32(o[0][nf],
                         __float_as_uint(s[0][k2][0]), __float_as_uint(s[0][k2][2]),
                         __float_as_uint(s[0][k2][1]), __float_as_uint(s[0][k2][3]), b0, b1);
                mma_tf32(o[1][nf],
                         __float_as_uint(s[1][k2][0]), __float_as_uint(s[1][k2][2]),
                         __float_as_uint(s[1][k2][1]), __float_as_uint(s[1][k2][3]), b0, b1);
            }
        }

        __syncthreads();   // all warps done reading buf cur before refilling it
        if (kt + 2 < 32) issue_tile(kt + 2, cur);
    }

    // ---- epilogue: reduce l across quad, normalize, add residual q ----
#pragma unroll
    for (int m = 0; m < 2; m++) {
        float l0 = ll[m][0], l1 = ll[m][1];
        l0 += __shfl_xor_sync(0xffffffffu, l0, 1);
        l0 += __shfl_xor_sync(0xffffffffu, l0, 2);
        l1 += __shfl_xor_sync(0xffffffffu, l1, 1);
        l1 += __shfl_xor_sync(0xffffffffu, l1, 2);
        float il0 = 1.f / l0, il1 = 1.f / l1;
        const size_t r0o = qbase + m * 16 + g;
        const size_t r1o = r0o + 8;
#pragma unroll
        for (int nf = 0; nf < 8; nf++) {
            int c = nf * 8 + 2 * t;
            float2 q0 = *reinterpret_cast<const float2*>(g_Q + r0o * DD + c);
            float2 q1 = *reinterpret_cast<const float2*>(g_Q + r1o * DD + c);
            *reinterpret_cast<float2*>(out + r0o * DD + c) =
                make_float2(o[m][nf][0] * il0 + q0.x, o[m][nf][1] * il0 + q0.y);
            *reinterpret_cast<float2*>(out + r1o * DD + c) =
                make_float2(o[m][nf][2] * il1 + q1.x, o[m][nf][3] * il1 + q1.y);
        }
    }
}

// ============================================================================
extern "C" void kernel_launch(void* const* d_in, const int* in_sizes, int n_in,
                              void* d_out, int out_size) {
    const float* x  = (const float*)d_in[0];
    const float* Wq = (const float*)d_in[1];
    const float* bq = (const float*)d_in[2];
    const float* Wk = (const float*)d_in[3];
    const float* bk = (const float*)d_in[4];
    const float* Wv = (const float*)d_in[5];
    const float* bv = (const float*)d_in[6];
    float* out = (float*)d_out;

    qkv_kernel<<<512, 384>>>(x, Wq, bq, Wk, bk, Wv, bv);
    attn_kernel<<<dim3(8, 64), 128>>>(out);
}

// round 17
// speedup vs baseline: 1.4008x; 1.3988x over previous
#include <cuda_runtime.h>
#include <cuda_bf16.h>
#include <cstdint>

// Problem constants
#define BB 64
#define NN 1024
#define CC 128
#define DD 64

// Scratch: Q, K fp32; V transposed bf16 [b][d][n]. __device__ globals.
__device__ float g_Q[BB * NN * DD];
__device__ float g_K[BB * NN * DD];
__device__ __nv_bfloat16 g_Vt[BB * DD * NN];

// Round fp32 -> tf32 (round-to-nearest), returned as float bit-pattern.
__device__ __forceinline__ float f2tf(float f) {
    uint32_t u;
    asm("cvt.rna.tf32.f32 %0, %1;" : "=r"(u) : "f"(f));
    return __uint_as_float(u);
}

// Pack two fp32 -> bf16x2 (lo = first element).
__device__ __forceinline__ uint32_t pack_bf16(float lo, float hi) {
    uint32_t d;
    asm("cvt.rn.bf16x2.f32 %0, %1, %2;" : "=r"(d) : "f"(hi), "f"(lo));
    return d;
}

__device__ __forceinline__ float ex2(float x) {
    float y;
    asm("ex2.approx.f32 %0, %1;" : "=f"(y) : "f"(x));
    return y;
}

// m16n8k8 tf32 MMA, fp32 accumulate. A row-major, B col-major.
__device__ __forceinline__ void mma_tf32(float* d,
                                         uint32_t a0, uint32_t a1, uint32_t a2, uint32_t a3,
                                         uint32_t b0, uint32_t b1) {
    asm volatile(
        "mma.sync.aligned.m16n8k8.row.col.f32.tf32.tf32.f32 "
        "{%0,%1,%2,%3}, {%4,%5,%6,%7}, {%8,%9}, {%0,%1,%2,%3};"
        : "+f"(d[0]), "+f"(d[1]), "+f"(d[2]), "+f"(d[3])
        : "r"(a0), "r"(a1), "r"(a2), "r"(a3), "r"(b0), "r"(b1));
}

// m16n8k16 bf16 MMA, fp32 accumulate.
__device__ __forceinline__ void mma_bf16(float* d,
                                         uint32_t a0, uint32_t a1, uint32_t a2, uint32_t a3,
                                         uint32_t b0, uint32_t b1) {
    asm volatile(
        "mma.sync.aligned.m16n8k16.row.col.f32.bf16.bf16.f32 "
        "{%0,%1,%2,%3}, {%4,%5,%6,%7}, {%8,%9}, {%0,%1,%2,%3};"
        : "+f"(d[0]), "+f"(d[1]), "+f"(d[2]), "+f"(d[3])
        : "r"(a0), "r"(a1), "r"(a2), "r"(a3), "r"(b0), "r"(b1));
}

// ============================================================================
// Kernel 1: QKV projection (R10 structure).  dst = relu(x @ W + b).
// grid (3, 512): matrix index fastest so x row-tiles stay L2-hot.
// Q, K stored fp32 row-major; V stored TRANSPOSED bf16 [b][d][n] for attn.
// ============================================================================
__global__ __launch_bounds__(128) void qkv_kernel(
    const float* __restrict__ x,
    const float* __restrict__ Wq, const float* __restrict__ bq,
    const float* __restrict__ Wk, const float* __restrict__ bk,
    const float* __restrict__ Wv, const float* __restrict__ bv)
{
    __shared__ float xs[128 * 36];   // x chunk [128 rows][32 k], stride 36
    __shared__ float ws[32 * 72];    // W chunk [32 k][64 n],   stride 72

    const int tid  = threadIdx.x;
    const int w    = tid >> 5;
    const int lane = tid & 31;
    const int g    = lane >> 2;
    const int t    = lane & 3;
    const int mat  = blockIdx.x;          // 0:Q 1:K 2:V
    const int r0   = blockIdx.y * 128;

    const float* W    = (mat == 0) ? Wq : (mat == 1) ? Wk : Wv;
    const float* bias = (mat == 0) ? bq : (mat == 1) ? bk : bv;

    float acc[2][8][4];
#pragma unroll
    for (int m = 0; m < 2; m++)
#pragma unroll
        for (int i = 0; i < 8; i++)
#pragma unroll
            for (int j = 0; j < 4; j++) acc[m][i][j] = 0.f;

    for (int kc = 0; kc < 4; kc++) {
        __syncthreads();
#pragma unroll
        for (int i = 0; i < 8; i++) {
            int v   = tid + i * 128;
            int row = v >> 3;
            int c4  = v & 7;
            float4 xv = *reinterpret_cast<const float4*>(
                x + (size_t)(r0 + row) * CC + kc * 32 + c4 * 4);
            *reinterpret_cast<float4*>(&xs[row * 36 + c4 * 4]) =
                make_float4(f2tf(xv.x), f2tf(xv.y), f2tf(xv.z), f2tf(xv.w));
        }
#pragma unroll
        for (int i = 0; i < 4; i++) {
            int v   = tid + i * 128;
            int row = v >> 4;
            int c4  = v & 15;
            float4 wv = *reinterpret_cast<const float4*>(
                W + (size_t)(kc * 32 + row) * DD + c4 * 4);
            *reinterpret_cast<float4*>(&ws[row * 72 + c4 * 4]) =
                make_float4(f2tf(wv.x), f2tf(wv.y), f2tf(wv.z), f2tf(wv.w));
        }
        __syncthreads();

#pragma unroll
        for (int ksi = 0; ksi < 4; ksi++) {
            uint32_t a[2][4];
#pragma unroll
            for (int m = 0; m < 2; m++) {
                int ar = (w * 32 + m * 16 + g) * 36 + ksi * 8 + t;
                a[m][0] = __float_as_uint(xs[ar]);
                a[m][1] = __float_as_uint(xs[ar + 8 * 36]);
                a[m][2] = __float_as_uint(xs[ar + 4]);
                a[m][3] = __float_as_uint(xs[ar + 8 * 36 + 4]);
            }
#pragma unroll
            for (int nf = 0; nf < 8; nf++) {
                uint32_t b0 = __float_as_uint(ws[(ksi * 8 + t)     * 72 + nf * 8 + g]);
                uint32_t b1 = __float_as_uint(ws[(ksi * 8 + t + 4) * 72 + nf * 8 + g]);
                mma_tf32(acc[0][nf], a[0][0], a[0][1], a[0][2], a[0][3], b0, b1);
                mma_tf32(acc[1][nf], a[1][0], a[1][1], a[1][2], a[1][3], b0, b1);
            }
        }
    }

    // Epilogue.
    float* dst = (mat == 0) ? g_Q : g_K;
#pragma unroll
    for (int m = 0; m < 2; m++) {
        const size_t rg = (size_t)r0 + w * 32 + m * 16 + g;
#pragma unroll
        for (int nf = 0; nf < 8; nf++) {
            int dcol = nf * 8 + 2 * t;
            float b0v = bias[dcol], b1v = bias[dcol + 1];
            float v00 = fmaxf(acc[m][nf][0] + b0v, 0.f);
            float v01 = fmaxf(acc[m][nf][1] + b1v, 0.f);
            float v10 = fmaxf(acc[m][nf][2] + b0v, 0.f);
            float v11 = fmaxf(acc[m][nf][3] + b1v, 0.f);
            if (mat != 2) {
                *reinterpret_cast<float2*>(dst + rg * DD + dcol)       = make_float2(v00, v01);
                *reinterpret_cast<float2*>(dst + (rg + 8) * DD + dcol) = make_float2(v10, v11);
            } else {
                // V: transposed bf16 [b][d][n]
                const size_t bidx = rg >> 10;
                const size_t n    = rg & 1023;
                __nv_bfloat16* vt = g_Vt + (bidx * DD) * NN;
                vt[(size_t)(dcol)     * NN + n]     = __float2bfloat16(v00);
                vt[(size_t)(dcol + 1) * NN + n]     = __float2bfloat16(v01);
                vt[(size_t)(dcol)     * NN + n + 8] = __float2bfloat16(v10);
                vt[(size_t)(dcol + 1) * NN + n + 8] = __float2bfloat16(v11);
            }
        }
    }
}

// ============================================================================
// Kernel 2: flash attention + residual.  out = softmax(Q Kt / 8) @ V + Q
// CTA = 128 q-rows (grid 8 x 64), 4 warps, warp = 32 rows (2 m-frags).
// Q in registers pre-scaled by 0.125*log2(e) -> P = exp2(S). S-phase tf32
// (K raw fp32, HW-truncated). PV in bf16 m16n8k16: the m16n8 S accumulator
// packs DIRECTLY into the bf16 A-fragment (no permutation, no smem).
// V tiles arrive pre-transposed bf16 from g_Vt. Register prefetch, 1 sync/tile.
// No max-tracking (q,k >= 0 bounds scores).
// ============================================================================
__global__ __launch_bounds__(128) void attn_kernel(float* __restrict__ out)
{
    __shared__ __align__(16) float    ksm[2][32 * 68];   // K tiles, raw fp32 [key][d]
    __shared__ __align__(16) uint32_t vs[2][64 * 36];    // V tiles, bf16x2 [d][key/2]

    const int tid  = threadIdx.x;
    const int w    = tid >> 5;
    const int lane = tid & 31;
    const int g    = lane >> 2;
    const int t    = lane & 3;
    const int b    = blockIdx.y;
    const int qt   = blockIdx.x;
    const size_t qbase = (size_t)b * NN + qt * 128 + w * 32;

    // K-load coords: 32 rows x 16 float4.
    const int lrow = tid >> 4;
    const int lc4  = tid & 15;
    const float* kbase = g_K + (size_t)b * NN * DD;
    // V-load coords: d = tid>>1, chunk h and h+2 (uint4 = 8 bf16 keys each).
    const int vd = tid >> 1;
    const int vh = tid & 1;
    const __nv_bfloat16* vtbase = g_Vt + ((size_t)b * DD + vd) * NN;

    // Q fragments in registers, scaled by 1/8 * log2(e).
    const float cq = 0.125f * 1.4426950408889634f;
    uint32_t qa[2][8][4];
#pragma unroll
    for (int m = 0; m < 2; m++) {
        const float* qb = g_Q + (qbase + m * 16) * DD;
#pragma unroll
        for (int ksi = 0; ksi < 8; ksi++) {
            qa[m][ksi][0] = __float_as_uint(f2tf(qb[(size_t)g * DD + ksi * 8 + t] * cq));
            qa[m][ksi][1] = __float_as_uint(f2tf(qb[(size_t)(g + 8) * DD + ksi * 8 + t] * cq));
            qa[m][ksi][2] = __float_as_uint(f2tf(qb[(size_t)g * DD + ksi * 8 + t + 4] * cq));
            qa[m][ksi][3] = __float_as_uint(f2tf(qb[(size_t)(g + 8) * DD + ksi * 8 + t + 4] * cq));
        }
    }

    float o[2][8][4];
#pragma unroll
    for (int m = 0; m < 2; m++)
#pragma unroll
        for (int i = 0; i < 8; i++)
#pragma unroll
            for (int j = 0; j < 4; j++) o[m][i][j] = 0.f;
    float ll[2][2] = {{0.f, 0.f}, {0.f, 0.f}};   // lane-local l partials [m][row-half]

    // Preload tile 0 into buffer 0.
#pragma unroll
    for (int i = 0; i < 4; i++) {
        int row = lrow + i * 8;
        float4 kv = *reinterpret_cast<const float4*>(kbase + row * DD + lc4 * 4);
        *reinterpret_cast<float4*>(&ksm[0][row * 68 + lc4 * 4]) = kv;
    }
    {
        uint4 v0 = *reinterpret_cast<const uint4*>(vtbase + vh * 8);
        uint4 v1 = *reinterpret_cast<const uint4*>(vtbase + (vh + 2) * 8);
        *reinterpret_cast<uint4*>(&vs[0][vd * 36 + vh * 4])       = v0;
        *reinterpret_cast<uint4*>(&vs[0][vd * 36 + (vh + 2) * 4]) = v1;
    }
    __syncthreads();

    for (int kt = 0; kt < 32; kt++) {
        const int cur = kt & 1, nxt = cur ^ 1;

        // Prefetch next tile gmem -> registers.
        float4 pk[4];
        uint4 pv0, pv1;
        if (kt < 31) {
            const float* kb = kbase + (size_t)(kt + 1) * 32 * DD;
            const __nv_bfloat16* vb = vtbase + (size_t)(kt + 1) * 32;
#pragma unroll
            for (int i = 0; i < 4; i++) {
                int row = lrow + i * 8;
                pk[i] = *reinterpret_cast<const float4*>(kb + row * DD + lc4 * 4);
            }
            pv0 = *reinterpret_cast<const uint4*>(vb + vh * 8);
            pv1 = *reinterpret_cast<const uint4*>(vb + (vh + 2) * 8);
        }

        // ---- S = (Q*c) @ K^T : 32x32 per warp (tf32), natural key order ----
        float s[2][4][4];
#pragma unroll
        for (int m = 0; m < 2; m++)
#pragma unroll
            for (int i = 0; i < 4; i++)
#pragma unroll
                for (int j = 0; j < 4; j++) s[m][i][j] = 0.f;
#pragma unroll
        for (int ksi = 0; ksi < 8; ksi++) {
#pragma unroll
            for (int nf = 0; nf < 4; nf++) {
                int kr = (nf * 8 + g) * 68 + ksi * 8 + t;
                uint32_t b0 = __float_as_uint(ksm[cur][kr]);
                uint32_t b1 = __float_as_uint(ksm[cur][kr + 4]);
                mma_tf32(s[0][nf], qa[0][ksi][0], qa[0][ksi][1], qa[0][ksi][2], qa[0][ksi][3], b0, b1);
                mma_tf32(s[1][nf], qa[1][ksi][0], qa[1][ksi][1], qa[1][ksi][2], qa[1][ksi][3], b0, b1);
            }
        }

        // ---- P = exp2(S); accumulate l; pack into bf16 A-fragments ----
        // S frag (m16n8): c0=(g,2t) c1=(g,2t+1) c2=(g+8,2t) c3=(g+8,2t+1)
        // bf16 A (m16k16): a0=(g,2t|2t+1) a1=(g+8,2t|2t+1) a2=(g,2t+8|2t+9) a3=(g+8,...)
        uint32_t pa[2][2][4];   // [m][k16-step j][a-reg]
#pragma unroll
        for (int m = 0; m < 2; m++) {
#pragma unroll
            for (int j = 0; j < 2; j++) {
#pragma unroll
                for (int h = 0; h < 2; h++) {   // nf = 2j + h
                    float e0 = ex2(s[m][2 * j + h][0]);
                    float e1 = ex2(s[m][2 * j + h][1]);
                    float e2 = ex2(s[m][2 * j + h][2]);
                    float e3 = ex2(s[m][2 * j + h][3]);
                    ll[m][0] += e0 + e1;
                    ll[m][1] += e2 + e3;
                    pa[m][j][h * 2 + 0] = pack_bf16(e0, e1);   // row g   (a0 / a2)
                    pa[m][j][h * 2 + 1] = pack_bf16(e2, e3);   // row g+8 (a1 / a3)
                }
            }
        }

        // ---- O += P @ V : bf16 m16n8k16, 2 k16-steps x 8 nf x 2 m ----
#pragma unroll
        for (int j = 0; j < 2; j++) {
#pragma unroll
            for (int nf = 0; nf < 8; nf++) {
                int va = (nf * 8 + g) * 36 + j * 8 + t;
                uint32_t b0 = vs[cur][va];
                uint32_t b1 = vs[cur][va + 4];
                mma_bf16(o[0][nf], pa[0][j][0], pa[0][j][1], pa[0][j][2], pa[0][j][3], b0, b1);
                mma_bf16(o[1][nf], pa[1][j][0], pa[1][j][1], pa[1][j][2], pa[1][j][3], b0, b1);
            }
        }

        // ---- drain prefetch into the other buffer ----
        if (kt < 31) {
#pragma unroll
            for (int i = 0; i < 4; i++) {
                int row = lrow + i * 8;
                *reinterpret_cast<float4*>(&ksm[nxt][row * 68 + lc4 * 4]) = pk[i];
            }
            *reinterpret_cast<uint4*>(&vs[nxt][vd * 36 + vh * 4])       = pv0;
            *reinterpret_cast<uint4*>(&vs[nxt][vd * 36 + (vh + 2) * 4]) = pv1;
        }
        __syncthreads();
    }

    // ---- epilogue: reduce l across quad, normalize, add residual q ----
#pragma unroll
    for (int m = 0; m < 2; m++) {
        float l0 = ll[m][0], l1 = ll[m][1];
        l0 += __shfl_xor_sync(0xffffffffu, l0, 1);
        l0 += __shfl_xor_sync(0xffffffffu, l0, 2);
        l1 += __shfl_xor_sync(0xffffffffu, l1, 1);
        l1 += __shfl_xor_sync(0xffffffffu, l1, 2);
        float il0 = 1.f / l0, il1 = 1.f / l1;
        const size_t r0o = qbase + m * 16 + g;
        const size_t r1o = r0o + 8;
#pragma unroll
        for (int nf = 0; nf < 8; nf++) {
            int c = nf * 8 + 2 * t;
            float2 q0 = *reinterpret_cast<const float2*>(g_Q + r0o * DD + c);
            float2 q1 = *reinterpret_cast<const float2*>(g_Q + r1o * DD + c);
            *reinterpret_cast<float2*>(out + r0o * DD + c) =
                make_float2(o[m][nf][0] * il0 + q0.x, o[m][nf][1] * il0 + q0.y);
            *reinterpret_cast<float2*>(out + r1o * DD + c) =
                make_float2(o[m][nf][2] * il1 + q1.x, o[m][nf][3] * il1 + q1.y);
        }
    }
}

// ============================================================================
extern "C" void kernel_launch(void* const* d_in, const int* in_sizes, int n_in,
                              void* d_out, int out_size) {
    const float* x  = (const float*)d_in[0];
    const float* Wq = (const float*)d_in[1];
    const float* bq = (const float*)d_in[2];
    const float* Wk = (const float*)d_in[3];
    const float* bk = (const float*)d_in[4];
    const float* Wv = (const float*)d_in[5];
    const float* bv = (const float*)d_in[6];
    float* out = (float*)d_out;

    qkv_kernel<<<dim3(3, 512), 128>>>(x, Wq, bq, Wk, bk, Wv, bv);
    attn_kernel<<<dim3(8, 64), 128>>>(out);
}